// round 14
// baseline (speedup 1.0000x reference)
#include <cuda_runtime.h>
#include <cfloat>

// N=8192 tokens, K=4096, D=1024.
//   idx[n] = argmax_k x[n,k]  (first-occurrence tie-break)
//   out[n,d] = W[d, idx[n]]
//
// K1: float4 transpose W [D,K] -> g_Wt [K,D], 1024 blocks, PDL trigger (R7).
// K2 (PDL consumer), 7168 blocks:
//   blocks 0..1023   -> tokens {2b, 2b+1}  (2 argmaxes pre-barrier = 32 KB
//                       of overlappable x-work each; these are dispatched
//                       first, concurrent with K1)
//   blocks 1024..7167 -> token b+1024      (R7's proven 1-token layout)
// One cudaGridDependencySynchronize, then gather(s) from L2-resident g_Wt.

#define NTOK 8192
#define KDIM 4096
#define DDIM 1024
#define TP_TILE 64
#define TP_BLOCKS ((KDIM / TP_TILE) * (DDIM / TP_TILE))   // 1024
#define DUAL 1024                                          // dual-token blocks
#define K2_BLOCKS (DUAL + (NTOK - 2 * DUAL))               // 7168

__device__ float g_Wt[(size_t)KDIM * DDIM];   // 16 MB scratch

// ---------------- K1: transpose, float4 both sides (R7 verbatim) ------------
__global__ void __launch_bounds__(256) transpose_kernel(const float* __restrict__ W)
{
#if __CUDA_ARCH__ >= 900
    cudaTriggerProgrammaticLaunchCompletion();   // let K2 co-schedule
#endif
    __shared__ float t[TP_TILE][TP_TILE + 1];
    const int bid = blockIdx.x;
    const int tid = threadIdx.x;
    const int k0 = (bid % (KDIM / TP_TILE)) * TP_TILE;
    const int d0 = (bid / (KDIM / TP_TILE)) * TP_TILE;
    const int tx = tid & 15;     // float4 lane along fast dim
    const int ty = tid >> 4;     // row 0..15

    #pragma unroll
    for (int i = 0; i < 4; ++i) {
        int r = ty + 16 * i;
        float4 v = __ldcs(reinterpret_cast<const float4*>(
            W + (size_t)(d0 + r) * KDIM + (k0 + 4 * tx)));
        t[r][4 * tx + 0] = v.x;
        t[r][4 * tx + 1] = v.y;
        t[r][4 * tx + 2] = v.z;
        t[r][4 * tx + 3] = v.w;
    }
    __syncthreads();

    #pragma unroll
    for (int i = 0; i < 4; ++i) {
        int r = ty + 16 * i;
        float4 v;
        v.x = t[4 * tx + 0][r];
        v.y = t[4 * tx + 1][r];
        v.z = t[4 * tx + 2][r];
        v.w = t[4 * tx + 3][r];
        *reinterpret_cast<float4*>(
            g_Wt + (size_t)(k0 + r) * DDIM + (d0 + 4 * tx)) = v;
    }
}

// ---------------- K2: fused argmax + gather, non-uniform tokens --------------
__global__ void __launch_bounds__(256) argmax_gather_kernel(
    const float* __restrict__ x, float* __restrict__ out)
{
    const int b    = blockIdx.x;
    const int tid  = threadIdx.x;
    const int warp = tid >> 5;
    const int lane = tid & 31;

    int t0, ntok;
    if (b < DUAL) { t0 = 2 * b;    ntok = 2; }
    else          { t0 = b + DUAL; ntok = 1; }

    __shared__ float s_val[8];
    __shared__ int   s_idx[8];
    __shared__ int   s_tok[2];

    // ---- pre-barrier: argmax for ntok tokens (reads only x, overlaps K1) ----
    for (int t = 0; t < ntok; ++t) {
        const int n = t0 + t;
        const float4* xr = reinterpret_cast<const float4*>(x + (size_t)n * KDIM);

        float best = -FLT_MAX;
        int   bi   = 0x7fffffff;

        #pragma unroll
        for (int it = 0; it < (KDIM / 4) / 256; ++it) {
            int c = tid + it * 256;
            float4 v = __ldcs(xr + c);
            int base = c * 4;
            if (v.x > best) { best = v.x; bi = base + 0; }
            if (v.y > best) { best = v.y; bi = base + 1; }
            if (v.z > best) { best = v.z; bi = base + 2; }
            if (v.w > best) { best = v.w; bi = base + 3; }
        }

        // warp reduce (smaller index wins ties)
        #pragma unroll
        for (int off = 16; off > 0; off >>= 1) {
            float ov = __shfl_down_sync(0xffffffffu, best, off);
            int   oi = __shfl_down_sync(0xffffffffu, bi,   off);
            if (ov > best || (ov == best && oi < bi)) { best = ov; bi = oi; }
        }

        if (lane == 0) { s_val[warp] = best; s_idx[warp] = bi; }
        __syncthreads();
        if (warp == 0) {
            best = (lane < 8) ? s_val[lane] : -FLT_MAX;
            bi   = (lane < 8) ? s_idx[lane] : 0x7fffffff;
            #pragma unroll
            for (int off = 4; off > 0; off >>= 1) {
                float ov = __shfl_down_sync(0xffffffffu, best, off);
                int   oi = __shfl_down_sync(0xffffffffu, bi,   off);
                if (ov > best || (ov == best && oi < bi)) { best = ov; bi = oi; }
            }
            if (lane == 0) s_tok[t] = bi;
        }
        __syncthreads();   // smem reuse + s_tok visibility
    }

    // ---- wait for K1 (transpose) completion + memory flush ----
#if __CUDA_ARCH__ >= 900
    cudaGridDependencySynchronize();
#endif

    // ---- coalesced row copies: out[n,:] = g_Wt[idx,:] (L2 hits) ----
    for (int t = 0; t < ntok; ++t) {
        const int idx = s_tok[t];
        const float4* src = reinterpret_cast<const float4*>(g_Wt + (size_t)idx * DDIM);
        float4* dst = reinterpret_cast<float4*>(out + (size_t)(t0 + t) * DDIM);
        __stcs(dst + tid, src[tid]);
    }
}

extern "C" void kernel_launch(void* const* d_in, const int* in_sizes, int n_in,
                              void* d_out, int out_size) {
    const float* x = (const float*)d_in[0];   // [N, K]
    const float* W = (const float*)d_in[1];   // [D, K]
    float* out = (float*)d_out;               // [N, D]

    transpose_kernel<<<TP_BLOCKS, 256>>>(W);

    cudaLaunchConfig_t cfg = {};
    cfg.gridDim  = dim3(K2_BLOCKS, 1, 1);   // 7168
    cfg.blockDim = dim3(256, 1, 1);
    cfg.dynamicSmemBytes = 0;
    cfg.stream = 0;
    cudaLaunchAttribute attr[1];
    attr[0].id = cudaLaunchAttributeProgrammaticStreamSerialization;
    attr[0].val.programmaticStreamSerializationAllowed = 1;
    cfg.attrs = attr;
    cfg.numAttrs = 1;
    cudaLaunchKernelEx(&cfg, argmax_gather_kernel, x, out);
}

// round 15
// speedup vs baseline: 1.0147x; 1.0147x over previous
#include <cuda_runtime.h>
#include <cfloat>

// N=8192 tokens, K=4096, D=1024.
//   idx[n] = argmax_k x[n,k]  (first-occurrence tie-break)
//   out[n,d] = W[d, idx[n]]
//
// K1 (register transpose, no smem/syncs): each thread owns a 4(d) x 8(k)
//     sub-block: 8 LDG.128 (each 32B sector fully consumed -> 16 MB DRAM
//     read, no amplification) + 8 STG.128 coalesced across the warp into
//     Wt rows. ~2 instr per 16B vs ~10 for the smem version -> ~2x-faster K1.
//     512 blocks + PDL trigger.
// K2: R7's proven fused argmax+gather, 8192 blocks x 1 token (PDL consumer).

#define NTOK 8192
#define KDIM 4096
#define DDIM 1024

__device__ float g_Wt[(size_t)KDIM * DDIM];   // 16 MB scratch

// ---------------- K1: register-blocked transpose ----------------
// Block: 256 thr = 8 warps. Block tile: k 64 x d 128.
// Warp w: k-slab k0+8w .. +7. Lane l: d rows d0+4l .. d0+4l+3.
#define T_KB 64
#define T_DB 128
#define T_BLOCKS ((KDIM / T_KB) * (DDIM / T_DB))   // 64 * 8 = 512

__global__ void __launch_bounds__(256) transpose_kernel(const float* __restrict__ W)
{
#if __CUDA_ARCH__ >= 900
    cudaTriggerProgrammaticLaunchCompletion();   // let K2 co-schedule
#endif
    const int tid  = threadIdx.x;
    const int warp = tid >> 5;
    const int lane = tid & 31;

    const int k0 = (blockIdx.x % (KDIM / T_KB)) * T_KB + warp * 8;
    const int d0 = (blockIdx.x / (KDIM / T_KB)) * T_DB;
    const int dr = d0 + 4 * lane;                // this thread's 4 d-rows

    // load 4 rows x 8 k (2 float4 per row) = full 32B sectors per row
    float4 a[4][2];
    #pragma unroll
    for (int i = 0; i < 4; ++i) {
        const float* row = W + (size_t)(dr + i) * KDIM + k0;
        a[i][0] = __ldcs(reinterpret_cast<const float4*>(row));
        a[i][1] = __ldcs(reinterpret_cast<const float4*>(row + 4));
    }

    // write 8 Wt rows; across the warp lanes cover d0..d0+127 contiguous
    #pragma unroll
    for (int c = 0; c < 2; ++c) {
        {   // j = 4c+0 : component .x
            float4 o = make_float4(a[0][c].x, a[1][c].x, a[2][c].x, a[3][c].x);
            *reinterpret_cast<float4*>(g_Wt + (size_t)(k0 + 4*c + 0) * DDIM + dr) = o;
        }
        {   // j = 4c+1 : component .y
            float4 o = make_float4(a[0][c].y, a[1][c].y, a[2][c].y, a[3][c].y);
            *reinterpret_cast<float4*>(g_Wt + (size_t)(k0 + 4*c + 1) * DDIM + dr) = o;
        }
        {   // j = 4c+2 : component .z
            float4 o = make_float4(a[0][c].z, a[1][c].z, a[2][c].z, a[3][c].z);
            *reinterpret_cast<float4*>(g_Wt + (size_t)(k0 + 4*c + 2) * DDIM + dr) = o;
        }
        {   // j = 4c+3 : component .w
            float4 o = make_float4(a[0][c].w, a[1][c].w, a[2][c].w, a[3][c].w);
            *reinterpret_cast<float4*>(g_Wt + (size_t)(k0 + 4*c + 3) * DDIM + dr) = o;
        }
    }
}

// ---------------- K2: fused argmax + row gather (R7 verbatim) ----------------
__global__ void __launch_bounds__(256) argmax_gather_kernel(
    const float* __restrict__ x, float* __restrict__ out)
{
    const int n   = blockIdx.x;
    const int tid = threadIdx.x;

    // ---- argmax phase: only reads x, overlaps K1 ----
    const float4* xr = reinterpret_cast<const float4*>(x + (size_t)n * KDIM);
    float best = -FLT_MAX;
    int   bi   = 0x7fffffff;

    #pragma unroll
    for (int it = 0; it < (KDIM / 4) / 256; ++it) {
        int c = tid + it * 256;
        float4 v = __ldcs(xr + c);
        int base = c * 4;
        if (v.x > best) { best = v.x; bi = base + 0; }
        if (v.y > best) { best = v.y; bi = base + 1; }
        if (v.z > best) { best = v.z; bi = base + 2; }
        if (v.w > best) { best = v.w; bi = base + 3; }
    }

    // warp reduce (smaller index wins ties)
    #pragma unroll
    for (int off = 16; off > 0; off >>= 1) {
        float ov = __shfl_down_sync(0xffffffffu, best, off);
        int   oi = __shfl_down_sync(0xffffffffu, bi,   off);
        if (ov > best || (ov == best && oi < bi)) { best = ov; bi = oi; }
    }

    // block reduce across 8 warps
    __shared__ float s_val[8];
    __shared__ int   s_idx[8];
    __shared__ int   s_final;
    int warp = tid >> 5;
    int lane = tid & 31;
    if (lane == 0) { s_val[warp] = best; s_idx[warp] = bi; }
    __syncthreads();
    if (warp == 0) {
        best = (lane < 8) ? s_val[lane] : -FLT_MAX;
        bi   = (lane < 8) ? s_idx[lane] : 0x7fffffff;
        #pragma unroll
        for (int off = 4; off > 0; off >>= 1) {
            float ov = __shfl_down_sync(0xffffffffu, best, off);
            int   oi = __shfl_down_sync(0xffffffffu, bi,   off);
            if (ov > best || (ov == best && oi < bi)) { best = ov; bi = oi; }
        }
        if (lane == 0) s_final = bi;
    }
    __syncthreads();
    const int idx = s_final;

    // ---- wait for K1 (transpose) completion + memory flush ----
#if __CUDA_ARCH__ >= 900
    cudaGridDependencySynchronize();
#endif

    // ---- coalesced row copy: out[n,:] = g_Wt[idx,:] ----
    const float4* src = reinterpret_cast<const float4*>(g_Wt + (size_t)idx * DDIM);
    float4*       dst = reinterpret_cast<float4*>(out + (size_t)n * DDIM);
    __stcs(dst + tid, src[tid]);
}

extern "C" void kernel_launch(void* const* d_in, const int* in_sizes, int n_in,
                              void* d_out, int out_size) {
    const float* x = (const float*)d_in[0];   // [N, K]
    const float* W = (const float*)d_in[1];   // [D, K]
    float* out = (float*)d_out;               // [N, D]

    transpose_kernel<<<T_BLOCKS, 256>>>(W);

    cudaLaunchConfig_t cfg = {};
    cfg.gridDim  = dim3(NTOK, 1, 1);
    cfg.blockDim = dim3(256, 1, 1);
    cfg.dynamicSmemBytes = 0;
    cfg.stream = 0;
    cudaLaunchAttribute attr[1];
    attr[0].id = cudaLaunchAttributeProgrammaticStreamSerialization;
    attr[0].val.programmaticStreamSerializationAllowed = 1;
    cfg.attrs = attr;
    cfg.numAttrs = 1;
    cudaLaunchKernelEx(&cfg, argmax_gather_kernel, x, out);
}